// round 10
// baseline (speedup 1.0000x reference)
#include <cuda_runtime.h>
#include <math.h>

// Problem dims (fixed by the reference):
//   inputs  : (4, 2, 96, 192, 192) float32
//   targets : (4, 1, 96, 192, 192) int32
#define Bn   4
#define Zd   96
#define Yd   192
#define Xd   192
#define YX   (Yd * Xd)            // 36864
#define WX   3                    // 192 bits = 3 x uint64 per row
#define WORDS (Bn * Zd * Yd * WX) // 221184 words per field
#define NVOX (Bn * Zd * YX)       // 14155776
#define BVOX ((long)Zd * YX)      // voxels per (b, c) volume
#define BVOXI (Zd * YX)           // int version

// Stage 1: 4 fused erosion iterations, halo 4.
#define ZT 16
#define YT 16
#define H  4
#define SZ (ZT + 2 * H)           // 24
#define SY (YT + 2 * H)           // 24
#define TW (SZ * SY * WX)         // 1728 words per tile buffer
#define TILES_Z (Zd / ZT)         // 6
#define TILES_Y (Yd / YT)         // 12
#define TILES_PER_B (TILES_Z * TILES_Y)      // 72
#define BLOCKS_PER_F (Bn * TILES_PER_B)      // 288
#define EGRID (2 * BLOCKS_PER_F)             // 576

// Stage 2: 16 fused erosion iterations (iters 5..20), halo 16.
#define H2 16
#define SZ2 (ZT + 2 * H2)         // 48
#define SY2 (YT + 2 * H2)         // 48
#define TW2 (SZ2 * SY2 * WX)      // 6912 words per buffer
#define E16_SMEM (2 * TW2 * 8)    // 110592 bytes dynamic smem

// Pack kernel: 16 voxels per thread (4 x float4 per stream), coalesced,
// all loads front-batched for MLP.
#define PQ   4                    // q-iterations
#define PBLK (256 * 4 * PQ)       // 4096 voxels per block
#define PACK_BLOCKS (NVOX / PBLK) // 3456

typedef unsigned long long u64;

// Bit fields: [parity][field][word]; field 0 = t, field 1 = 1 - t.
__device__ u64    g_bits[2][2][WORDS];   // ~7.1 MB
__device__ double g_S0[Bn];     // sum p * t           per batch
__device__ double g_Sp[Bn];     // sum p               per batch
__device__ double g_accA[Bn];   // sum_i sum_{alive_i(t)} p
__device__ double g_accB[Bn];   // sum_i sum_{alive_i(1-t)} p
__device__ int    g_fg[Bn];     // foreground voxel count per batch
__device__ int    g_flag1[2];   // per-field: alive after stage-1 erosion
__device__ unsigned g_done;     // last-block counter for fused finalize

__device__ __forceinline__ float sig_p(float x0, float x1) {
    // softmax channel 1 of {x0, x1} = sigmoid(x1 - x0)
    //                               = 0.5 * tanh(0.5*(x1 - x0)) + 0.5
    float r;
    asm("tanh.approx.f32 %0, %1;" : "=f"(r) : "f"(0.5f * (x1 - x0)));
    return fmaf(0.5f, r, 0.5f);
}

// Pack targets into bits (t and ~t), count fg per batch, and compute
// S0 = sum(p*t), Sp = sum(p) per batch. Coalesced streaming float4/int4
// loads, front-batched (12 LDG.128 in flight per thread).
__global__ void __launch_bounds__(256) k_pack(const float* __restrict__ inp,
                                              const int* __restrict__ tgt) {
    long base = (long)blockIdx.x * PBLK;
    int b = (int)(base / BVOX);          // uniform per block (BVOX % PBLK == 0)
    long vloc = base - (long)b * BVOX;

    const int4*   tg4 = (const int4*)(tgt + base);
    const float4* a4  = (const float4*)(inp + (long)b * 2 * BVOX + vloc);
    const float4* b4  = (const float4*)((const float*)a4 + BVOX);

    int tid = threadIdx.x;
    int lane = tid & 31;
    int warp = tid >> 5;

    int4   tv[PQ];
    float4 xa[PQ], xb[PQ];
    #pragma unroll
    for (int q = 0; q < PQ; q++) {
        int vi = q * 256 + tid;          // vector index; voxel = 4*vi
        tv[q] = __ldcs(tg4 + vi);
        xa[q] = __ldcs(a4 + vi);
        xb[q] = __ldcs(b4 + vi);
    }

    float sp = 0.0f, s0 = 0.0f;
    int fg = 0;

    #pragma unroll
    for (int q = 0; q < PQ; q++) {
        float pa = sig_p(xa[q].x, xb[q].x);
        float pb = sig_p(xa[q].y, xb[q].y);
        float pc = sig_p(xa[q].z, xb[q].z);
        float pd = sig_p(xa[q].w, xb[q].w);
        sp += pa + pb + pc + pd;
        unsigned m = 0;
        if (tv[q].x) { s0 += pa; m |= 1u; }
        if (tv[q].y) { s0 += pb; m |= 2u; }
        if (tv[q].z) { s0 += pc; m |= 4u; }
        if (tv[q].w) { s0 += pd; m |= 8u; }

        // Assemble u64 word from 16 consecutive lanes' nibbles.
        unsigned v = m | (__shfl_down_sync(0xffffffffu, m, 1) << 4);
        v |= __shfl_down_sync(0xffffffffu, v, 2) << 8;
        v |= __shfl_down_sync(0xffffffffu, v, 4) << 16;
        u64 w = (u64)v | ((u64)__shfl_down_sync(0xffffffffu, v, 8) << 32);

        if ((lane & 15) == 0) {          // lanes 0 and 16 hold valid words
            long wi = (base >> 6) + q * 16 + warp * 2 + (lane >> 4);
            g_bits[0][0][wi] = w;
            g_bits[0][1][wi] = ~w;
            fg += __popcll(w);
        }
    }

    #pragma unroll
    for (int oo = 16; oo > 0; oo >>= 1) {
        s0 += __shfl_down_sync(0xffffffffu, s0, oo);
        sp += __shfl_down_sync(0xffffffffu, sp, oo);
        fg += __shfl_down_sync(0xffffffffu, fg, oo);
    }
    __shared__ float sh0[8], shp[8];
    __shared__ int shfg[8];
    if (lane == 0) { sh0[warp] = s0; shp[warp] = sp; shfg[warp] = fg; }
    __syncthreads();
    if (tid == 0) {
        float t0 = 0.0f, tp = 0.0f; int tf = 0;
        #pragma unroll
        for (int ww = 0; ww < 8; ww++) { t0 += sh0[ww]; tp += shp[ww]; tf += shfg[ww]; }
        atomicAdd(&g_S0[b], (double)t0);
        atomicAdd(&g_Sp[b], (double)tp);
        if (tf) atomicAdd(&g_fg[b], tf);
    }
}

// Fused erosion iterations j = 1..NJ starting from g_bits[SRC&1], writing
// g_bits[(SRC&1)^1]. Shared-memory double buffer with halo NJ. Accumulates
// the p-weighted popcount of each alive set over the block's ownership
// region. Early-terminates dead tiles.
// STAGE0: source aliveness from g_fg[b] (and dst must be zeroed on skip,
//         since stage 2 may read it). Otherwise source aliveness from
//         g_flag1[f]; on skip nothing reads dst, so plain return.
// Launched with programmatic stream serialization: the grid may start while
// the predecessor kernel is still running; cudaGridDependencySynchronize()
// gates the first access to predecessor-written memory.
template <int NJ, int HH, int SSZ, int SSY, int SRC, bool STAGE0>
__device__ __forceinline__ void erode_body(
    u64* bufA, u64* bufB, const float* __restrict__ inp, int fblocks_idx) {
    __shared__ float shs[8];

    const int TWLOC = SSZ * SSY * WX;
    int f = fblocks_idx / BLOCKS_PER_F;

    int rem = fblocks_idx % BLOCKS_PER_F;
    int b  = rem / TILES_PER_B;
    int t  = rem % TILES_PER_B;
    int tz = t / TILES_Y, ty = t % TILES_Y;
    int z0 = tz * ZT, y0 = ty * YT;

    const u64* gsrc = g_bits[SRC & 1][f];
    u64*       gdst = g_bits[(SRC & 1) ^ 1][f];

    int tid = threadIdx.x;

    // Wait for the predecessor kernel's writes to be visible. (No-op when
    // launched without programmatic serialization.)
    cudaGridDependencySynchronize();

    bool skip;
    if (STAGE0) {
        int fgb = g_fg[b];
        skip = (f == 0) ? (fgb == 0) : (fgb == BVOXI);
    } else {
        skip = (g_flag1[f] == 0);
    }
    if (skip) {
        if (STAGE0) {
            // Source field empty for this batch -> eroded output is empty.
            // Must write zeros: stage 2 may read this region.
            for (int i = tid; i < ZT * YT * WX; i += 256) {
                int k  = i % WX;
                int rr = i / WX;
                int dy = rr % YT;
                int dz = rr / YT;
                gdst[((long)(b * Zd + z0 + dz) * Yd + (y0 + dy)) * WX + k] = 0ULL;
            }
        }
        return;
    }

    // Load tile + halo; out-of-domain rows are all-ones (inf padding neutral).
    for (int i = tid; i < TWLOC; i += 256) {
        int k  = i % WX;
        int rr = i / WX;
        int dy = rr % SSY;
        int dz = rr / SSY;
        int z = z0 + dz - HH, y = y0 + dy - HH;
        u64 v = ~0ULL;
        if ((unsigned)z < (unsigned)Zd && (unsigned)y < (unsigned)Yd)
            v = gsrc[((long)(b * Zd + z) * Yd + y) * WX + k];
        bufA[i] = v;
    }
    __syncthreads();

    u64* cur = bufA;
    u64* nxt = bufB;
    float s = 0.0f;
    bool dead = false;
    int ownAny = 0;

    for (int j = 1; j <= NJ; j++) {
        int W  = SSY - 2 * j;
        int Rj = (SSZ - 2 * j) * W * WX;
        int alive = 0, ownAlive = 0;

        for (int i = tid; i < Rj; i += 256) {
            int k  = i % WX;
            int rr = i / WX;
            int dy = j + rr % W;
            int dz = j + rr / W;
            int z = z0 + dz - HH, y = y0 + dy - HH;
            bool indom = ((unsigned)z < (unsigned)Zd) &&
                         ((unsigned)y < (unsigned)Yd);
            u64 acc = ~0ULL;
            if (indom) {
                #pragma unroll
                for (int dz2 = -1; dz2 <= 1; dz2++) {
                    #pragma unroll
                    for (int dy2 = -1; dy2 <= 1; dy2++) {
                        const u64* row = cur + ((dz + dz2) * SSY + (dy + dy2)) * WX;
                        u64 c  = row[k];
                        u64 lt = (k > 0) ? row[k - 1] : ~0ULL;
                        u64 rt = (k < 2) ? row[k + 1] : ~0ULL;
                        acc &= c & ((c >> 1) | (rt << 63))
                                 & ((c << 1) | (lt >> 63));
                    }
                }
                if (acc) {
                    alive = 1;
                    bool own = (dz >= HH && dz < HH + ZT &&
                                dy >= HH && dy < HH + YT);
                    if (own) {
                        ownAlive = 1;
                        long in0 = (long)(b * 2) * BVOX + (long)z * YX
                                 + (long)y * Xd + k * 64;
                        u64 mm = acc;
                        while (mm) {
                            int bit = __ffsll((long long)mm) - 1;
                            mm &= mm - 1;
                            s += sig_p(inp[in0 + bit], inp[in0 + BVOX + bit]);
                        }
                    }
                }
            }
            nxt[(dz * SSY + dy) * WX + k] = acc;
        }

        int any = __syncthreads_or(alive);
        if (STAGE0 && j == NJ) ownAny = __syncthreads_or(ownAlive);
        u64* tmp = cur; cur = nxt; nxt = tmp;
        if (!any) { dead = true; break; }
    }

    // Write ownership region of the final bitmap.
    for (int i = tid; i < ZT * YT * WX; i += 256) {
        int k  = i % WX;
        int rr = i / WX;
        int dy = HH + rr % YT;
        int dz = HH + rr / YT;
        int z = z0 + dz - HH, y = y0 + dy - HH;
        u64 v = dead ? 0ULL : cur[(dz * SSY + dy) * WX + k];
        gdst[((long)(b * Zd + z) * Yd + y) * WX + k] = v;
    }

    // Rare: only tiles still alive after NJ iterations store the flag.
    if (STAGE0 && !dead && ownAny && tid == 0) g_flag1[f] = 1;

    // Block-reduce s and accumulate.
    int lane = tid & 31, warp = tid >> 5;
    #pragma unroll
    for (int oo = 16; oo > 0; oo >>= 1)
        s += __shfl_down_sync(0xffffffffu, s, oo);
    if (lane == 0) shs[warp] = s;
    __syncthreads();
    if (tid == 0) {
        float tot = 0.0f;
        #pragma unroll
        for (int ww = 0; ww < 8; ww++) tot += shs[ww];
        if (tot != 0.0f)
            atomicAdd(f ? &g_accB[b] : &g_accA[b], (double)tot);
    }
}

// Stage 1: iterations 1..4 (halo 4, static smem).
__global__ void __launch_bounds__(256) k_erode4(const float* __restrict__ inp) {
    __shared__ u64 bufA[TW], bufB[TW];
    erode_body<4, H, SZ, SY, 0, true>(bufA, bufB, inp, blockIdx.x);
}

// Stage 2: iterations 5..20 (halo 16, dynamic smem). Normally flag-exits.
// The LAST block to finish computes the loss with warp-PARALLEL loads
// (one memory round trip, not a serial pointer chase), writes d_out, and
// resets all device state for the next graph replay (globals are
// zero-initialized, so the very first call is covered).
__global__ void __launch_bounds__(256) k_erode16(const float* __restrict__ inp,
                                                 float* __restrict__ out) {
    extern __shared__ u64 dyn[];
    erode_body<16, H2, SZ2, SY2, 1, false>(dyn, dyn + TW2, inp, blockIdx.x);

    __syncthreads();
    __shared__ int s_last;
    if (threadIdx.x == 0) {
        __threadfence();
        unsigned old = atomicAdd(&g_done, 1u);
        s_last = (old == EGRID - 1u) ? 1 : 0;
    }
    __syncthreads();
    if (s_last && threadIdx.x < 32) {
        int lane = threadIdx.x;
        __threadfence();   // acquire: see all other blocks' atomics

        // Parallel load of all accumulators: lanes 0..15 -> the 4 double
        // arrays, lanes 16..19 -> g_fg (as double). One round trip.
        double v = 0.0;
        if (lane < 16) {
            const double* arrs[4] = { g_S0, g_Sp, g_accA, g_accB };
            v = arrs[lane >> 2][lane & 3];
        } else if (lane < 20) {
            v = (double)g_fg[lane & 3];
        }

        // Lane 0 gathers via 64-bit shuffles and computes the loss.
        double tot = 0.0;
        #pragma unroll
        for (int b = 0; b < Bn; b++) {
            double s0v = __shfl_sync(0xffffffffu, v, 0 * 4 + b);
            double spv = __shfl_sync(0xffffffffu, v, 1 * 4 + b);
            double aav = __shfl_sync(0xffffffffu, v, 2 * 4 + b);
            double abv = __shfl_sync(0xffffffffu, v, 3 * 4 + b);
            double fgv = __shfl_sync(0xffffffffu, v, 16 + b);
            tot += (fgv == 0.0) ? spv : (s0v - aav + abv);
        }
        if (lane == 0)
            out[0] = (float)(tot / (double)NVOX);

        __syncwarp();
        // Parallel reset for the next replay.
        if (lane < 16) {
            double* arrs[4] = { g_S0, g_Sp, g_accA, g_accB };
            arrs[lane >> 2][lane & 3] = 0.0;
        } else if (lane < 20) {
            g_fg[lane & 3] = 0;
        } else if (lane < 22) {
            g_flag1[lane - 20] = 0;
        }
        __threadfence();
        if (lane == 0) atomicExch(&g_done, 0u);
    }
}

extern "C" void kernel_launch(void* const* d_in, const int* in_sizes, int n_in,
                              void* d_out, int out_size) {
    // inputs (2*NVOX floats) first, targets (NVOX ints) second; guard by size.
    const float* inp;
    const int*   tgt;
    if (in_sizes[0] >= in_sizes[1]) {
        inp = (const float*)d_in[0];
        tgt = (const int*)d_in[1];
    } else {
        inp = (const float*)d_in[1];
        tgt = (const int*)d_in[0];
    }

    cudaFuncSetAttribute(k_erode16,
                         cudaFuncAttributeMaxDynamicSharedMemorySize, E16_SMEM);

    // Node 1: pack (plain launch).
    k_pack<<<PACK_BLOCKS, 256>>>(inp, tgt);

    // Nodes 2-3: programmatic dependent launches — each grid spins up while
    // its predecessor drains; cudaGridDependencySynchronize() inside the
    // kernel gates data consumption.
    cudaLaunchAttribute attr[1];
    attr[0].id = cudaLaunchAttributeProgrammaticStreamSerialization;
    attr[0].val.programmaticStreamSerializationAllowed = 1;

    cudaLaunchConfig_t cfg = {};
    cfg.blockDim = {256, 1, 1};
    cfg.attrs = attr;
    cfg.numAttrs = 1;
    cfg.stream = 0;

    cfg.gridDim = {EGRID, 1, 1};
    cfg.dynamicSmemBytes = 0;
    cudaLaunchKernelEx(&cfg, k_erode4, inp);

    cfg.dynamicSmemBytes = E16_SMEM;
    cudaLaunchKernelEx(&cfg, k_erode16, inp, (float*)d_out);
}

// round 11
// speedup vs baseline: 1.0756x; 1.0756x over previous
#include <cuda_runtime.h>
#include <math.h>

// Problem dims (fixed by the reference):
//   inputs  : (4, 2, 96, 192, 192) float32
//   targets : (4, 1, 96, 192, 192) int32
#define Bn   4
#define Zd   96
#define Yd   192
#define Xd   192
#define YX   (Yd * Xd)            // 36864
#define WX   3                    // 192 bits = 3 x uint64 per row
#define WORDS (Bn * Zd * Yd * WX) // 221184 words per field
#define NVOX (Bn * Zd * YX)       // 14155776
#define BVOX ((long)Zd * YX)      // voxels per (b, c) volume
#define BVOXI (Zd * YX)           // int version

// Stage 1: 4 fused erosion iterations, halo 4.
#define ZT 16
#define YT 16
#define H  4
#define SZ (ZT + 2 * H)           // 24
#define SY (YT + 2 * H)           // 24
#define TW (SZ * SY * WX)         // 1728 words per tile buffer
#define TILES_Z (Zd / ZT)         // 6
#define TILES_Y (Yd / YT)         // 12
#define TILES_PER_B (TILES_Z * TILES_Y)      // 72
#define BLOCKS_PER_F (Bn * TILES_PER_B)      // 288
#define EGRID (2 * BLOCKS_PER_F)             // 576

// Stage 2: 16 fused erosion iterations (iters 5..20), halo 16.
#define H2 16
#define SZ2 (ZT + 2 * H2)         // 48
#define SY2 (YT + 2 * H2)         // 48
#define TW2 (SZ2 * SY2 * WX)      // 6912 words per buffer
#define E16_SMEM (2 * TW2 * 8)    // 110592 bytes dynamic smem

// Pack kernel: 16 voxels per thread (4 x float4 per stream), coalesced,
// all loads front-batched for MLP.
#define PQ   4                    // q-iterations
#define PBLK (256 * 4 * PQ)       // 4096 voxels per block
#define PACK_BLOCKS (NVOX / PBLK) // 3456

typedef unsigned long long u64;

// Bit fields: [parity][field][word]; field 0 = t, field 1 = 1 - t.
__device__ u64    g_bits[2][2][WORDS];   // ~7.1 MB
__device__ double g_S0[Bn];     // sum p * t           per batch
__device__ double g_Sp[Bn];     // sum p               per batch
__device__ double g_accA[Bn];   // sum_i sum_{alive_i(t)} p
__device__ double g_accB[Bn];   // sum_i sum_{alive_i(1-t)} p
__device__ int    g_fg[Bn];     // foreground voxel count per batch
__device__ int    g_flag1[2];   // per-field: alive after stage-1 erosion

__device__ __forceinline__ float sig_p(float x0, float x1) {
    // softmax channel 1 of {x0, x1} = sigmoid(x1 - x0)
    //                               = 0.5 * tanh(0.5*(x1 - x0)) + 0.5
    float r;
    asm("tanh.approx.f32 %0, %1;" : "=f"(r) : "f"(0.5f * (x1 - x0)));
    return fmaf(0.5f, r, 0.5f);
}

// Pack targets into bits (t and ~t), count fg per batch, and compute
// S0 = sum(p*t), Sp = sum(p) per batch. Coalesced streaming float4/int4
// loads, front-batched (12 LDG.128 in flight per thread).
__global__ void __launch_bounds__(256) k_pack(const float* __restrict__ inp,
                                              const int* __restrict__ tgt) {
    long base = (long)blockIdx.x * PBLK;
    int b = (int)(base / BVOX);          // uniform per block (BVOX % PBLK == 0)
    long vloc = base - (long)b * BVOX;

    const int4*   tg4 = (const int4*)(tgt + base);
    const float4* a4  = (const float4*)(inp + (long)b * 2 * BVOX + vloc);
    const float4* b4  = (const float4*)((const float*)a4 + BVOX);

    int tid = threadIdx.x;
    int lane = tid & 31;
    int warp = tid >> 5;

    int4   tv[PQ];
    float4 xa[PQ], xb[PQ];
    #pragma unroll
    for (int q = 0; q < PQ; q++) {
        int vi = q * 256 + tid;          // vector index; voxel = 4*vi
        tv[q] = __ldcs(tg4 + vi);
        xa[q] = __ldcs(a4 + vi);
        xb[q] = __ldcs(b4 + vi);
    }

    float sp = 0.0f, s0 = 0.0f;
    int fg = 0;

    #pragma unroll
    for (int q = 0; q < PQ; q++) {
        float pa = sig_p(xa[q].x, xb[q].x);
        float pb = sig_p(xa[q].y, xb[q].y);
        float pc = sig_p(xa[q].z, xb[q].z);
        float pd = sig_p(xa[q].w, xb[q].w);
        sp += pa + pb + pc + pd;
        unsigned m = 0;
        if (tv[q].x) { s0 += pa; m |= 1u; }
        if (tv[q].y) { s0 += pb; m |= 2u; }
        if (tv[q].z) { s0 += pc; m |= 4u; }
        if (tv[q].w) { s0 += pd; m |= 8u; }

        // Assemble u64 word from 16 consecutive lanes' nibbles.
        unsigned v = m | (__shfl_down_sync(0xffffffffu, m, 1) << 4);
        v |= __shfl_down_sync(0xffffffffu, v, 2) << 8;
        v |= __shfl_down_sync(0xffffffffu, v, 4) << 16;
        u64 w = (u64)v | ((u64)__shfl_down_sync(0xffffffffu, v, 8) << 32);

        if ((lane & 15) == 0) {          // lanes 0 and 16 hold valid words
            long wi = (base >> 6) + q * 16 + warp * 2 + (lane >> 4);
            g_bits[0][0][wi] = w;
            g_bits[0][1][wi] = ~w;
            fg += __popcll(w);
        }
    }

    #pragma unroll
    for (int oo = 16; oo > 0; oo >>= 1) {
        s0 += __shfl_down_sync(0xffffffffu, s0, oo);
        sp += __shfl_down_sync(0xffffffffu, sp, oo);
        fg += __shfl_down_sync(0xffffffffu, fg, oo);
    }
    __shared__ float sh0[8], shp[8];
    __shared__ int shfg[8];
    if (lane == 0) { sh0[warp] = s0; shp[warp] = sp; shfg[warp] = fg; }
    __syncthreads();
    if (tid == 0) {
        float t0 = 0.0f, tp = 0.0f; int tf = 0;
        #pragma unroll
        for (int ww = 0; ww < 8; ww++) { t0 += sh0[ww]; tp += shp[ww]; tf += shfg[ww]; }
        atomicAdd(&g_S0[b], (double)t0);
        atomicAdd(&g_Sp[b], (double)tp);
        if (tf) atomicAdd(&g_fg[b], tf);
    }
}

// Fused erosion iterations j = 1..NJ starting from g_bits[SRC&1], writing
// g_bits[(SRC&1)^1]. Shared-memory double buffer with halo NJ. Accumulates
// the p-weighted popcount of each alive set over the block's ownership
// region. Early-terminates dead tiles.
// STAGE0: source aliveness from g_fg[b] (and dst must be zeroed on skip,
//         since stage 2 may read it). Otherwise source aliveness from
//         g_flag1[f]; on skip nothing reads dst, so plain return.
// Launched with programmatic stream serialization: the grid may start while
// the predecessor kernel is still running; cudaGridDependencySynchronize()
// gates the first access to predecessor-written memory.
template <int NJ, int HH, int SSZ, int SSY, int SRC, bool STAGE0>
__device__ __forceinline__ void erode_body(
    u64* bufA, u64* bufB, const float* __restrict__ inp, int fblocks_idx) {
    __shared__ float shs[8];

    const int TWLOC = SSZ * SSY * WX;
    int f = fblocks_idx / BLOCKS_PER_F;

    int rem = fblocks_idx % BLOCKS_PER_F;
    int b  = rem / TILES_PER_B;
    int t  = rem % TILES_PER_B;
    int tz = t / TILES_Y, ty = t % TILES_Y;
    int z0 = tz * ZT, y0 = ty * YT;

    const u64* gsrc = g_bits[SRC & 1][f];
    u64*       gdst = g_bits[(SRC & 1) ^ 1][f];

    int tid = threadIdx.x;

    // Wait for the predecessor kernel's writes to be visible. (No-op when
    // launched without programmatic serialization.)
    cudaGridDependencySynchronize();

    bool skip;
    if (STAGE0) {
        int fgb = g_fg[b];
        skip = (f == 0) ? (fgb == 0) : (fgb == BVOXI);
    } else {
        skip = (g_flag1[f] == 0);
    }
    if (skip) {
        if (STAGE0) {
            // Source field empty for this batch -> eroded output is empty.
            // Must write zeros: stage 2 may read this region.
            for (int i = tid; i < ZT * YT * WX; i += 256) {
                int k  = i % WX;
                int rr = i / WX;
                int dy = rr % YT;
                int dz = rr / YT;
                gdst[((long)(b * Zd + z0 + dz) * Yd + (y0 + dy)) * WX + k] = 0ULL;
            }
        }
        return;
    }

    // Load tile + halo; out-of-domain rows are all-ones (inf padding neutral).
    for (int i = tid; i < TWLOC; i += 256) {
        int k  = i % WX;
        int rr = i / WX;
        int dy = rr % SSY;
        int dz = rr / SSY;
        int z = z0 + dz - HH, y = y0 + dy - HH;
        u64 v = ~0ULL;
        if ((unsigned)z < (unsigned)Zd && (unsigned)y < (unsigned)Yd)
            v = gsrc[((long)(b * Zd + z) * Yd + y) * WX + k];
        bufA[i] = v;
    }
    __syncthreads();

    u64* cur = bufA;
    u64* nxt = bufB;
    float s = 0.0f;
    bool dead = false;
    int ownAny = 0;

    for (int j = 1; j <= NJ; j++) {
        int W  = SSY - 2 * j;
        int Rj = (SSZ - 2 * j) * W * WX;
        int alive = 0, ownAlive = 0;

        for (int i = tid; i < Rj; i += 256) {
            int k  = i % WX;
            int rr = i / WX;
            int dy = j + rr % W;
            int dz = j + rr / W;
            int z = z0 + dz - HH, y = y0 + dy - HH;
            bool indom = ((unsigned)z < (unsigned)Zd) &&
                         ((unsigned)y < (unsigned)Yd);
            u64 acc = ~0ULL;
            if (indom) {
                #pragma unroll
                for (int dz2 = -1; dz2 <= 1; dz2++) {
                    #pragma unroll
                    for (int dy2 = -1; dy2 <= 1; dy2++) {
                        const u64* row = cur + ((dz + dz2) * SSY + (dy + dy2)) * WX;
                        u64 c  = row[k];
                        u64 lt = (k > 0) ? row[k - 1] : ~0ULL;
                        u64 rt = (k < 2) ? row[k + 1] : ~0ULL;
                        acc &= c & ((c >> 1) | (rt << 63))
                                 & ((c << 1) | (lt >> 63));
                    }
                }
                if (acc) {
                    alive = 1;
                    bool own = (dz >= HH && dz < HH + ZT &&
                                dy >= HH && dy < HH + YT);
                    if (own) {
                        ownAlive = 1;
                        long in0 = (long)(b * 2) * BVOX + (long)z * YX
                                 + (long)y * Xd + k * 64;
                        u64 mm = acc;
                        while (mm) {
                            int bit = __ffsll((long long)mm) - 1;
                            mm &= mm - 1;
                            s += sig_p(inp[in0 + bit], inp[in0 + BVOX + bit]);
                        }
                    }
                }
            }
            nxt[(dz * SSY + dy) * WX + k] = acc;
        }

        int any = __syncthreads_or(alive);
        if (STAGE0 && j == NJ) ownAny = __syncthreads_or(ownAlive);
        u64* tmp = cur; cur = nxt; nxt = tmp;
        if (!any) { dead = true; break; }
    }

    // Write ownership region of the final bitmap.
    for (int i = tid; i < ZT * YT * WX; i += 256) {
        int k  = i % WX;
        int rr = i / WX;
        int dy = HH + rr % YT;
        int dz = HH + rr / YT;
        int z = z0 + dz - HH, y = y0 + dy - HH;
        u64 v = dead ? 0ULL : cur[(dz * SSY + dy) * WX + k];
        gdst[((long)(b * Zd + z) * Yd + y) * WX + k] = v;
    }

    // Rare: only tiles still alive after NJ iterations store the flag.
    if (STAGE0 && !dead && ownAny && tid == 0) g_flag1[f] = 1;

    // Block-reduce s and accumulate.
    int lane = tid & 31, warp = tid >> 5;
    #pragma unroll
    for (int oo = 16; oo > 0; oo >>= 1)
        s += __shfl_down_sync(0xffffffffu, s, oo);
    if (lane == 0) shs[warp] = s;
    __syncthreads();
    if (tid == 0) {
        float tot = 0.0f;
        #pragma unroll
        for (int ww = 0; ww < 8; ww++) tot += shs[ww];
        if (tot != 0.0f)
            atomicAdd(f ? &g_accB[b] : &g_accA[b], (double)tot);
    }
}

// Stage 1: iterations 1..4 (halo 4, static smem).
__global__ void __launch_bounds__(256) k_erode4(const float* __restrict__ inp) {
    __shared__ u64 bufA[TW], bufB[TW];
    erode_body<4, H, SZ, SY, 0, true>(bufA, bufB, inp, blockIdx.x);
}

// Stage 2: iterations 5..20 (halo 16, dynamic smem). Normally flag-exits.
__global__ void __launch_bounds__(256) k_erode16(const float* __restrict__ inp) {
    extern __shared__ u64 dyn[];
    erode_body<16, H2, SZ2, SY2, 1, false>(dyn, dyn + TW2, inp, blockIdx.x);
}

// Emits the loss with warp-PARALLEL loads (one memory round trip instead of
// ~20 serially-dependent ones), then resets all device state in parallel so
// the next call starts from zeroed state (globals are zero-initialized,
// covering the very first call).
__global__ void k_final(float* out) {
    cudaGridDependencySynchronize();
    int lane = threadIdx.x;

    // Parallel load: lanes 0..15 -> the 4 double arrays, 16..19 -> g_fg.
    double v = 0.0;
    if (lane < 16) {
        const double* p = (lane >> 2) == 0 ? g_S0
                        : (lane >> 2) == 1 ? g_Sp
                        : (lane >> 2) == 2 ? g_accA : g_accB;
        v = p[lane & 3];
    } else if (lane < 20) {
        v = (double)g_fg[lane & 3];
    }

    // Lane 0 gathers via shuffles and computes the loss.
    double tot = 0.0;
    #pragma unroll
    for (int b = 0; b < Bn; b++) {
        double s0v = __shfl_sync(0xffffffffu, v, 0 * 4 + b);
        double spv = __shfl_sync(0xffffffffu, v, 1 * 4 + b);
        double aav = __shfl_sync(0xffffffffu, v, 2 * 4 + b);
        double abv = __shfl_sync(0xffffffffu, v, 3 * 4 + b);
        double fgv = __shfl_sync(0xffffffffu, v, 16 + b);
        tot += (fgv == 0.0) ? spv : (s0v - aav + abv);
    }
    if (lane == 0)
        out[0] = (float)(tot / (double)NVOX);

    // Parallel reset for the next call.
    if (lane < 16) {
        double* p = (lane >> 2) == 0 ? g_S0
                  : (lane >> 2) == 1 ? g_Sp
                  : (lane >> 2) == 2 ? g_accA : g_accB;
        p[lane & 3] = 0.0;
    } else if (lane < 20) {
        g_fg[lane & 3] = 0;
    } else if (lane < 22) {
        g_flag1[lane - 20] = 0;
    }
}

extern "C" void kernel_launch(void* const* d_in, const int* in_sizes, int n_in,
                              void* d_out, int out_size) {
    // inputs (2*NVOX floats) first, targets (NVOX ints) second; guard by size.
    const float* inp;
    const int*   tgt;
    if (in_sizes[0] >= in_sizes[1]) {
        inp = (const float*)d_in[0];
        tgt = (const int*)d_in[1];
    } else {
        inp = (const float*)d_in[1];
        tgt = (const int*)d_in[0];
    }

    cudaFuncSetAttribute(k_erode16,
                         cudaFuncAttributeMaxDynamicSharedMemorySize, E16_SMEM);

    // Node 1: pack (plain launch).
    k_pack<<<PACK_BLOCKS, 256>>>(inp, tgt);

    // Nodes 2-4: programmatic dependent launches — each grid spins up while
    // its predecessor drains; cudaGridDependencySynchronize() inside the
    // kernel gates data consumption.
    cudaLaunchAttribute attr[1];
    attr[0].id = cudaLaunchAttributeProgrammaticStreamSerialization;
    attr[0].val.programmaticStreamSerializationAllowed = 1;

    cudaLaunchConfig_t cfg = {};
    cfg.blockDim = {256, 1, 1};
    cfg.attrs = attr;
    cfg.numAttrs = 1;
    cfg.stream = 0;

    cfg.gridDim = {EGRID, 1, 1};
    cfg.dynamicSmemBytes = 0;
    cudaLaunchKernelEx(&cfg, k_erode4, inp);

    cfg.dynamicSmemBytes = E16_SMEM;
    cudaLaunchKernelEx(&cfg, k_erode16, inp);

    cfg.gridDim = {1, 1, 1};
    cfg.blockDim = {32, 1, 1};
    cfg.dynamicSmemBytes = 0;
    cudaLaunchKernelEx(&cfg, k_final, (float*)d_out);
}

// round 12
// speedup vs baseline: 1.0762x; 1.0006x over previous
#include <cuda_runtime.h>
#include <math.h>

// Problem dims (fixed by the reference):
//   inputs  : (4, 2, 96, 192, 192) float32
//   targets : (4, 1, 96, 192, 192) int32
#define Bn   4
#define Zd   96
#define Yd   192
#define Xd   192
#define YX   (Yd * Xd)            // 36864
#define WX   3                    // 192 bits = 3 x uint64 per row
#define WORDS (Bn * Zd * Yd * WX) // 221184 words per field
#define NVOX (Bn * Zd * YX)       // 14155776
#define BVOX ((long)Zd * YX)      // voxels per (b, c) volume
#define BVOXI (Zd * YX)           // int version

// Stage 1: 4 fused erosion iterations, halo 4.
#define ZT 16
#define YT 16
#define H  4
#define SZ (ZT + 2 * H)           // 24
#define SY (YT + 2 * H)           // 24
#define TW (SZ * SY * WX)         // 1728 words per tile buffer
#define TILES_Z (Zd / ZT)         // 6
#define TILES_Y (Yd / YT)         // 12
#define TILES_PER_B (TILES_Z * TILES_Y)      // 72
#define BLOCKS_PER_F (Bn * TILES_PER_B)      // 288
#define EGRID (2 * BLOCKS_PER_F)             // 576

// Stage 2: 16 fused erosion iterations (iters 5..20), halo 16.
#define H2 16
#define SZ2 (ZT + 2 * H2)         // 48
#define SY2 (YT + 2 * H2)         // 48
#define TW2 (SZ2 * SY2 * WX)      // 6912 words per buffer
#define E16_SMEM (2 * TW2 * 8)    // 110592 bytes dynamic smem

// Pack kernel: 512 threads/block, 8 voxels per thread (2 x float4 per
// stream) -> fewer live registers, higher occupancy, same coalescing.
#define PT   512                  // threads per pack block
#define PQ   2                    // q-iterations
#define PBLK (PT * 4 * PQ)        // 4096 voxels per block
#define PACK_BLOCKS (NVOX / PBLK) // 3456

typedef unsigned long long u64;

// Bit fields: [parity][field][word]; field 0 = t, field 1 = 1 - t.
__device__ u64    g_bits[2][2][WORDS];   // ~7.1 MB
__device__ double g_S0[Bn];     // sum p * t           per batch
__device__ double g_Sp[Bn];     // sum p               per batch
__device__ double g_accA[Bn];   // sum_i sum_{alive_i(t)} p
__device__ double g_accB[Bn];   // sum_i sum_{alive_i(1-t)} p
__device__ int    g_fg[Bn];     // foreground voxel count per batch
__device__ int    g_flag1[2];   // per-field: alive after stage-1 erosion

__device__ __forceinline__ float sig_p(float x0, float x1) {
    // softmax channel 1 of {x0, x1} = sigmoid(x1 - x0)
    //                               = 0.5 * tanh(0.5*(x1 - x0)) + 0.5
    float r;
    asm("tanh.approx.f32 %0, %1;" : "=f"(r) : "f"(0.5f * (x1 - x0)));
    return fmaf(0.5f, r, 0.5f);
}

// Pack targets into bits (t and ~t), count fg per batch, and compute
// S0 = sum(p*t), Sp = sum(p) per batch. Coalesced streaming float4/int4
// loads, front-batched (6 LDG.128 in flight per thread), 512-thread
// blocks for 75% occupancy.
__global__ void __launch_bounds__(PT) k_pack(const float* __restrict__ inp,
                                             const int* __restrict__ tgt) {
    long base = (long)blockIdx.x * PBLK;
    int b = (int)(base / BVOX);          // uniform per block (BVOX % PBLK == 0)
    long vloc = base - (long)b * BVOX;

    const int4*   tg4 = (const int4*)(tgt + base);
    const float4* a4  = (const float4*)(inp + (long)b * 2 * BVOX + vloc);
    const float4* b4  = (const float4*)((const float*)a4 + BVOX);

    int tid = threadIdx.x;
    int lane = tid & 31;
    int warp = tid >> 5;

    int4   tv[PQ];
    float4 xa[PQ], xb[PQ];
    #pragma unroll
    for (int q = 0; q < PQ; q++) {
        int vi = q * PT + tid;           // vector index; voxel = 4*vi
        tv[q] = __ldcs(tg4 + vi);
        xa[q] = __ldcs(a4 + vi);
        xb[q] = __ldcs(b4 + vi);
    }

    float sp = 0.0f, s0 = 0.0f;
    int fg = 0;

    #pragma unroll
    for (int q = 0; q < PQ; q++) {
        float pa = sig_p(xa[q].x, xb[q].x);
        float pb = sig_p(xa[q].y, xb[q].y);
        float pc = sig_p(xa[q].z, xb[q].z);
        float pd = sig_p(xa[q].w, xb[q].w);
        sp += pa + pb + pc + pd;
        unsigned m = 0;
        if (tv[q].x) { s0 += pa; m |= 1u; }
        if (tv[q].y) { s0 += pb; m |= 2u; }
        if (tv[q].z) { s0 += pc; m |= 4u; }
        if (tv[q].w) { s0 += pd; m |= 8u; }

        // Assemble u64 word from 16 consecutive lanes' nibbles.
        unsigned v = m | (__shfl_down_sync(0xffffffffu, m, 1) << 4);
        v |= __shfl_down_sync(0xffffffffu, v, 2) << 8;
        v |= __shfl_down_sync(0xffffffffu, v, 4) << 16;
        u64 w = (u64)v | ((u64)__shfl_down_sync(0xffffffffu, v, 8) << 32);

        if ((lane & 15) == 0) {          // lanes 0 and 16 hold valid words
            long wi = (base >> 6) + q * (PT / 16) + warp * 2 + (lane >> 4);
            g_bits[0][0][wi] = w;
            g_bits[0][1][wi] = ~w;
            fg += __popcll(w);
        }
    }

    #pragma unroll
    for (int oo = 16; oo > 0; oo >>= 1) {
        s0 += __shfl_down_sync(0xffffffffu, s0, oo);
        sp += __shfl_down_sync(0xffffffffu, sp, oo);
        fg += __shfl_down_sync(0xffffffffu, fg, oo);
    }
    __shared__ float sh0[PT / 32], shp[PT / 32];
    __shared__ int shfg[PT / 32];
    if (lane == 0) { sh0[warp] = s0; shp[warp] = sp; shfg[warp] = fg; }
    __syncthreads();
    if (tid == 0) {
        float t0 = 0.0f, tp = 0.0f; int tf = 0;
        #pragma unroll
        for (int ww = 0; ww < PT / 32; ww++) {
            t0 += sh0[ww]; tp += shp[ww]; tf += shfg[ww];
        }
        atomicAdd(&g_S0[b], (double)t0);
        atomicAdd(&g_Sp[b], (double)tp);
        if (tf) atomicAdd(&g_fg[b], tf);
    }
}

// Fused erosion iterations j = 1..NJ starting from g_bits[SRC&1], writing
// g_bits[(SRC&1)^1]. Shared-memory double buffer with halo NJ. Accumulates
// the p-weighted popcount of each alive set over the block's ownership
// region. Early-terminates dead tiles.
// STAGE0: source aliveness from g_fg[b] (and dst must be zeroed on skip,
//         since stage 2 may read it). Otherwise source aliveness from
//         g_flag1[f]; on skip nothing reads dst, so plain return.
// Launched with programmatic stream serialization: the grid may start while
// the predecessor kernel is still running; cudaGridDependencySynchronize()
// gates the first access to predecessor-written memory.
template <int NJ, int HH, int SSZ, int SSY, int SRC, bool STAGE0>
__device__ __forceinline__ void erode_body(
    u64* bufA, u64* bufB, const float* __restrict__ inp, int fblocks_idx) {
    __shared__ float shs[8];

    const int TWLOC = SSZ * SSY * WX;
    int f = fblocks_idx / BLOCKS_PER_F;

    int rem = fblocks_idx % BLOCKS_PER_F;
    int b  = rem / TILES_PER_B;
    int t  = rem % TILES_PER_B;
    int tz = t / TILES_Y, ty = t % TILES_Y;
    int z0 = tz * ZT, y0 = ty * YT;

    const u64* gsrc = g_bits[SRC & 1][f];
    u64*       gdst = g_bits[(SRC & 1) ^ 1][f];

    int tid = threadIdx.x;

    // Wait for the predecessor kernel's writes to be visible. (No-op when
    // launched without programmatic serialization.)
    cudaGridDependencySynchronize();

    bool skip;
    if (STAGE0) {
        int fgb = g_fg[b];
        skip = (f == 0) ? (fgb == 0) : (fgb == BVOXI);
    } else {
        skip = (g_flag1[f] == 0);
    }
    if (skip) {
        if (STAGE0) {
            // Source field empty for this batch -> eroded output is empty.
            // Must write zeros: stage 2 may read this region.
            for (int i = tid; i < ZT * YT * WX; i += 256) {
                int k  = i % WX;
                int rr = i / WX;
                int dy = rr % YT;
                int dz = rr / YT;
                gdst[((long)(b * Zd + z0 + dz) * Yd + (y0 + dy)) * WX + k] = 0ULL;
            }
        }
        return;
    }

    // Load tile + halo; out-of-domain rows are all-ones (inf padding neutral).
    for (int i = tid; i < TWLOC; i += 256) {
        int k  = i % WX;
        int rr = i / WX;
        int dy = rr % SSY;
        int dz = rr / SSY;
        int z = z0 + dz - HH, y = y0 + dy - HH;
        u64 v = ~0ULL;
        if ((unsigned)z < (unsigned)Zd && (unsigned)y < (unsigned)Yd)
            v = gsrc[((long)(b * Zd + z) * Yd + y) * WX + k];
        bufA[i] = v;
    }
    __syncthreads();

    u64* cur = bufA;
    u64* nxt = bufB;
    float s = 0.0f;
    bool dead = false;
    int ownAny = 0;

    for (int j = 1; j <= NJ; j++) {
        int W  = SSY - 2 * j;
        int Rj = (SSZ - 2 * j) * W * WX;
        int alive = 0, ownAlive = 0;

        for (int i = tid; i < Rj; i += 256) {
            int k  = i % WX;
            int rr = i / WX;
            int dy = j + rr % W;
            int dz = j + rr / W;
            int z = z0 + dz - HH, y = y0 + dy - HH;
            bool indom = ((unsigned)z < (unsigned)Zd) &&
                         ((unsigned)y < (unsigned)Yd);
            u64 acc = ~0ULL;
            if (indom) {
                #pragma unroll
                for (int dz2 = -1; dz2 <= 1; dz2++) {
                    #pragma unroll
                    for (int dy2 = -1; dy2 <= 1; dy2++) {
                        const u64* row = cur + ((dz + dz2) * SSY + (dy + dy2)) * WX;
                        u64 c  = row[k];
                        u64 lt = (k > 0) ? row[k - 1] : ~0ULL;
                        u64 rt = (k < 2) ? row[k + 1] : ~0ULL;
                        acc &= c & ((c >> 1) | (rt << 63))
                                 & ((c << 1) | (lt >> 63));
                    }
                }
                if (acc) {
                    alive = 1;
                    bool own = (dz >= HH && dz < HH + ZT &&
                                dy >= HH && dy < HH + YT);
                    if (own) {
                        ownAlive = 1;
                        long in0 = (long)(b * 2) * BVOX + (long)z * YX
                                 + (long)y * Xd + k * 64;
                        u64 mm = acc;
                        while (mm) {
                            int bit = __ffsll((long long)mm) - 1;
                            mm &= mm - 1;
                            s += sig_p(inp[in0 + bit], inp[in0 + BVOX + bit]);
                        }
                    }
                }
            }
            nxt[(dz * SSY + dy) * WX + k] = acc;
        }

        int any = __syncthreads_or(alive);
        if (STAGE0 && j == NJ) ownAny = __syncthreads_or(ownAlive);
        u64* tmp = cur; cur = nxt; nxt = tmp;
        if (!any) { dead = true; break; }
    }

    // Write ownership region of the final bitmap.
    for (int i = tid; i < ZT * YT * WX; i += 256) {
        int k  = i % WX;
        int rr = i / WX;
        int dy = HH + rr % YT;
        int dz = HH + rr / YT;
        int z = z0 + dz - HH, y = y0 + dy - HH;
        u64 v = dead ? 0ULL : cur[(dz * SSY + dy) * WX + k];
        gdst[((long)(b * Zd + z) * Yd + y) * WX + k] = v;
    }

    // Rare: only tiles still alive after NJ iterations store the flag.
    if (STAGE0 && !dead && ownAny && tid == 0) g_flag1[f] = 1;

    // Block-reduce s and accumulate.
    int lane = tid & 31, warp = tid >> 5;
    #pragma unroll
    for (int oo = 16; oo > 0; oo >>= 1)
        s += __shfl_down_sync(0xffffffffu, s, oo);
    if (lane == 0) shs[warp] = s;
    __syncthreads();
    if (tid == 0) {
        float tot = 0.0f;
        #pragma unroll
        for (int ww = 0; ww < 8; ww++) tot += shs[ww];
        if (tot != 0.0f)
            atomicAdd(f ? &g_accB[b] : &g_accA[b], (double)tot);
    }
}

// Stage 1: iterations 1..4 (halo 4, static smem).
__global__ void __launch_bounds__(256) k_erode4(const float* __restrict__ inp) {
    __shared__ u64 bufA[TW], bufB[TW];
    erode_body<4, H, SZ, SY, 0, true>(bufA, bufB, inp, blockIdx.x);
}

// Stage 2: iterations 5..20 (halo 16, dynamic smem). Normally flag-exits.
__global__ void __launch_bounds__(256) k_erode16(const float* __restrict__ inp) {
    extern __shared__ u64 dyn[];
    erode_body<16, H2, SZ2, SY2, 1, false>(dyn, dyn + TW2, inp, blockIdx.x);
}

// Emits the loss with warp-PARALLEL loads (one memory round trip instead of
// ~20 serially-dependent ones), then resets all device state in parallel so
// the next call starts from zeroed state (globals are zero-initialized,
// covering the very first call).
__global__ void k_final(float* out) {
    cudaGridDependencySynchronize();
    int lane = threadIdx.x;

    // Parallel load: lanes 0..15 -> the 4 double arrays, 16..19 -> g_fg.
    double v = 0.0;
    if (lane < 16) {
        const double* p = (lane >> 2) == 0 ? g_S0
                        : (lane >> 2) == 1 ? g_Sp
                        : (lane >> 2) == 2 ? g_accA : g_accB;
        v = p[lane & 3];
    } else if (lane < 20) {
        v = (double)g_fg[lane & 3];
    }

    // Lane 0 gathers via shuffles and computes the loss.
    double tot = 0.0;
    #pragma unroll
    for (int b = 0; b < Bn; b++) {
        double s0v = __shfl_sync(0xffffffffu, v, 0 * 4 + b);
        double spv = __shfl_sync(0xffffffffu, v, 1 * 4 + b);
        double aav = __shfl_sync(0xffffffffu, v, 2 * 4 + b);
        double abv = __shfl_sync(0xffffffffu, v, 3 * 4 + b);
        double fgv = __shfl_sync(0xffffffffu, v, 16 + b);
        tot += (fgv == 0.0) ? spv : (s0v - aav + abv);
    }
    if (lane == 0)
        out[0] = (float)(tot / (double)NVOX);

    // Parallel reset for the next call.
    if (lane < 16) {
        double* p = (lane >> 2) == 0 ? g_S0
                  : (lane >> 2) == 1 ? g_Sp
                  : (lane >> 2) == 2 ? g_accA : g_accB;
        p[lane & 3] = 0.0;
    } else if (lane < 20) {
        g_fg[lane & 3] = 0;
    } else if (lane < 22) {
        g_flag1[lane - 20] = 0;
    }
}

extern "C" void kernel_launch(void* const* d_in, const int* in_sizes, int n_in,
                              void* d_out, int out_size) {
    // inputs (2*NVOX floats) first, targets (NVOX ints) second; guard by size.
    const float* inp;
    const int*   tgt;
    if (in_sizes[0] >= in_sizes[1]) {
        inp = (const float*)d_in[0];
        tgt = (const int*)d_in[1];
    } else {
        inp = (const float*)d_in[1];
        tgt = (const int*)d_in[0];
    }

    cudaFuncSetAttribute(k_erode16,
                         cudaFuncAttributeMaxDynamicSharedMemorySize, E16_SMEM);

    // Node 1: pack (plain launch).
    k_pack<<<PACK_BLOCKS, PT>>>(inp, tgt);

    // Nodes 2-4: programmatic dependent launches — each grid spins up while
    // its predecessor drains; cudaGridDependencySynchronize() inside the
    // kernel gates data consumption.
    cudaLaunchAttribute attr[1];
    attr[0].id = cudaLaunchAttributeProgrammaticStreamSerialization;
    attr[0].val.programmaticStreamSerializationAllowed = 1;

    cudaLaunchConfig_t cfg = {};
    cfg.blockDim = {256, 1, 1};
    cfg.attrs = attr;
    cfg.numAttrs = 1;
    cfg.stream = 0;

    cfg.gridDim = {EGRID, 1, 1};
    cfg.dynamicSmemBytes = 0;
    cudaLaunchKernelEx(&cfg, k_erode4, inp);

    cfg.dynamicSmemBytes = E16_SMEM;
    cudaLaunchKernelEx(&cfg, k_erode16, inp);

    cfg.gridDim = {1, 1, 1};
    cfg.blockDim = {32, 1, 1};
    cfg.dynamicSmemBytes = 0;
    cudaLaunchKernelEx(&cfg, k_final, (float*)d_out);
}